// round 1
// baseline (speedup 1.0000x reference)
#include <cuda_runtime.h>

#define LDIM 80
#define RDIM 80
#define BATCH 128
#define UD 128
#define CD 32
#define DD 416       // 3U + C
#define NOUT 896     // 3U + 4U
#define QPAD 420     // 420 % 32 == 4 -> conflict-free fragment LDS
#define NDIAG (LDIM + RDIM - 1)

// Rotating h storage: slot d%3 holds h of all cells on diagonal d.
__device__ float g_h[3][LDIM][BATCH][UD];             // ~15.7 MB
// Per-diagonal GEMM1 logits scratch, indexed by cell-in-diagonal.
__device__ float g_logits[LDIM][BATCH][NOUT];         // ~36.7 MB

__device__ __forceinline__ unsigned f2tf(float x) {
    unsigned u;
    asm("cvt.rna.tf32.f32 %0, %1;" : "=r"(u) : "f"(x));
    return u;
}

__device__ __forceinline__ void mma8(float* c, const unsigned* a, const unsigned* b) {
    asm volatile(
        "mma.sync.aligned.m16n8k8.row.col.f32.tf32.tf32.f32 "
        "{%0,%1,%2,%3}, {%4,%5,%6,%7}, {%8,%9}, {%0,%1,%2,%3};\n"
        : "+f"(c[0]), "+f"(c[1]), "+f"(c[2]), "+f"(c[3])
        : "r"(a[0]), "r"(a[1]), "r"(a[2]), "r"(a[3]), "r"(b[0]), "r"(b[1]));
}

// ---------------------------------------------------------------------------
// Kernel A: logits[cell][b][0..895] = q @ [Wr;Wz]^T + [br;bz]
// q = [h_top(128) | h_left(128) | h_diag(128) | s_ij(32)]
// grid: (ncells, 7 n-chunks of 128), 256 threads.
// ---------------------------------------------------------------------------
__global__ __launch_bounds__(256) void gemm1_kernel(
    const float* __restrict__ inputs, const float* __restrict__ Wr,
    const float* __restrict__ br, const float* __restrict__ Wz,
    const float* __restrict__ bz, int d, int l0)
{
    extern __shared__ unsigned qs[];   // [128][QPAD], tf32 bit patterns
    const int ci = blockIdx.x;
    const int l  = l0 + ci;
    const int rr = d - l;
    const int p1 = (d + 2) % 3;  // diag d-1
    const int p2 = (d + 1) % 3;  // diag d-2
    const float* htop  = (l > 0)           ? &g_h[p1][l-1][0][0] : (const float*)0;
    const float* hleft = (rr > 0)          ? &g_h[p1][l  ][0][0] : (const float*)0;
    const float* hdiag = (l > 0 && rr > 0) ? &g_h[p2][l-1][0][0] : (const float*)0;
    const int tid = threadIdx.x;

    // Build q in smem (tf32-rounded). 128 rows x 104 float4 segments.
    for (int idx = tid; idx < BATCH * 104; idx += 256) {
        const int b = idx / 104;
        const int k = (idx - b * 104) * 4;
        float v0, v1, v2, v3;
        if (k < 384) {
            const float* src; int kk;
            if (k < 128)      { src = htop;  kk = k; }
            else if (k < 256) { src = hleft; kk = k - 128; }
            else              { src = hdiag; kk = k - 256; }
            if (src) {
                float4 t = *(const float4*)(src + b * UD + kk);
                v0 = t.x; v1 = t.y; v2 = t.z; v3 = t.w;
            } else { v0 = v1 = v2 = v3 = 0.f; }
        } else {
            const int c = k - 384;
            const float* sp = inputs + (((size_t)b * CD + c) * LDIM + l) * RDIM + rr;
            v0 = sp[0];
            v1 = sp[LDIM * RDIM];
            v2 = sp[2 * LDIM * RDIM];
            v3 = sp[3 * LDIM * RDIM];
        }
        unsigned* q = qs + b * QPAD + k;
        q[0] = f2tf(v0); q[1] = f2tf(v1); q[2] = f2tf(v2); q[3] = f2tf(v3);
    }
    __syncthreads();

    const int warp = tid >> 5, lane = tid & 31;
    const int lane4 = lane >> 2, kc = lane & 3;
    const int wm = (warp & 1) * 64;                     // m base (batch rows)
    const int jbase = blockIdx.y * 128 + (warp >> 1) * 32;  // output-col base

    const float* wrow[4];
#pragma unroll
    for (int nt = 0; nt < 4; ++nt) {
        const int j = jbase + nt * 8 + lane4;
        wrow[nt] = (j < 384) ? (Wr + (size_t)j * DD) : (Wz + (size_t)(j - 384) * DD);
    }

    float acc[4][4][4];
#pragma unroll
    for (int mt = 0; mt < 4; ++mt)
#pragma unroll
        for (int nt = 0; nt < 4; ++nt)
#pragma unroll
            for (int i = 0; i < 4; ++i) acc[mt][nt][i] = 0.f;

#pragma unroll 1
    for (int k0 = 0; k0 < DD; k0 += 8) {
        unsigned af[4][4];
#pragma unroll
        for (int mt = 0; mt < 4; ++mt) {
            const unsigned* q0 = qs + (wm + mt * 16 + lane4) * QPAD + k0 + kc;
            af[mt][0] = q0[0];
            af[mt][2] = q0[4];
            af[mt][1] = q0[8 * QPAD];
            af[mt][3] = q0[8 * QPAD + 4];
        }
        unsigned bf[4][2];
#pragma unroll
        for (int nt = 0; nt < 4; ++nt) {
            bf[nt][0] = f2tf(wrow[nt][k0 + kc]);
            bf[nt][1] = f2tf(wrow[nt][k0 + kc + 4]);
        }
#pragma unroll
        for (int mt = 0; mt < 4; ++mt)
#pragma unroll
            for (int nt = 0; nt < 4; ++nt)
                mma8(acc[mt][nt], af[mt], bf[nt]);
    }

    float* lgbase = &g_logits[ci][0][0];
#pragma unroll
    for (int mt = 0; mt < 4; ++mt) {
#pragma unroll
        for (int nt = 0; nt < 4; ++nt) {
            const int row = wm + mt * 16 + lane4;
            const int col = jbase + nt * 8 + (lane & 3) * 2;
            const float b0 = (col < 384)     ? br[col]       : bz[col - 384];
            const float b1 = (col + 1 < 384) ? br[col + 1]   : bz[col + 1 - 384];
            float* dst = lgbase + row * NOUT + col;
            dst[0] = acc[mt][nt][0] + b0;
            dst[1] = acc[mt][nt][1] + b1;
            dst += 8 * NOUT;
            dst[0] = acc[mt][nt][2] + b0;
            dst[1] = acc[mt][nt][3] + b1;
        }
    }
}

// ---------------------------------------------------------------------------
// Kernel B: gates + hU GEMM + h update.
// A2 = [sig(r)*h_left | sig(r)*h_top | sig(r)*h_diag | s_ij]  (64 x 416)
// hU+Wij fused: B-rows = [WU(u, 0..383) | Wij(u, 0..31)]
// grid: (ncells, 2 batch halves), 256 threads.
// ---------------------------------------------------------------------------
__global__ __launch_bounds__(256) void cell_update_kernel(
    const float* __restrict__ inputs, const float* __restrict__ Wij,
    const float* __restrict__ bij, const float* __restrict__ WU,
    float* __restrict__ out, int d, int l0)
{
    extern __shared__ unsigned a2s[];  // [64][QPAD]
    const int ci = blockIdx.x;
    const int l  = l0 + ci;
    const int rr = d - l;
    const int b0 = blockIdx.y * 64;
    const int p1 = (d + 2) % 3, p2 = (d + 1) % 3, pc = d % 3;
    const float* hl = (rr > 0)          ? &g_h[p1][l  ][0][0] : (const float*)0;
    const float* ht = (l > 0)           ? &g_h[p1][l-1][0][0] : (const float*)0;
    const float* hd = (l > 0 && rr > 0) ? &g_h[p2][l-1][0][0] : (const float*)0;
    const float* lgbase = &g_logits[ci][0][0];
    const int tid = threadIdx.x;

    for (int idx = tid; idx < 64 * 104; idx += 256) {
        const int bl = idx / 104;
        const int k  = (idx - bl * 104) * 4;
        const int b  = b0 + bl;
        float v0, v1, v2, v3;
        if (k < 384) {
            const float* hsrc; int kk;
            if (k < 128)      { hsrc = hl; kk = k; }
            else if (k < 256) { hsrc = ht; kk = k - 128; }
            else              { hsrc = hd; kk = k - 256; }
            float4 lg = *(const float4*)(lgbase + b * NOUT + k);
            float4 hv;
            if (hsrc) hv = *(const float4*)(hsrc + b * UD + kk);
            else      hv = make_float4(0.f, 0.f, 0.f, 0.f);
            v0 = hv.x / (1.f + __expf(-lg.x));
            v1 = hv.y / (1.f + __expf(-lg.y));
            v2 = hv.z / (1.f + __expf(-lg.z));
            v3 = hv.w / (1.f + __expf(-lg.w));
        } else {
            const int c = k - 384;
            const float* sp = inputs + (((size_t)b * CD + c) * LDIM + l) * RDIM + rr;
            v0 = sp[0];
            v1 = sp[LDIM * RDIM];
            v2 = sp[2 * LDIM * RDIM];
            v3 = sp[3 * LDIM * RDIM];
        }
        unsigned* q = a2s + bl * QPAD + k;
        q[0] = f2tf(v0); q[1] = f2tf(v1); q[2] = f2tf(v2); q[3] = f2tf(v3);
    }
    __syncthreads();

    const int warp = tid >> 5, lane = tid & 31;
    const int lane4 = lane >> 2, kc = lane & 3;
    const int wm = (warp & 1) * 32;
    const int wn = (warp >> 1) * 32;

    const float* pWU[4];
    const float* pWij[4];
#pragma unroll
    for (int nt = 0; nt < 4; ++nt) {
        const int u = wn + nt * 8 + lane4;
        pWU[nt]  = WU  + (size_t)u * 384;
        pWij[nt] = Wij + (size_t)u * 32;
    }

    float acc[2][4][4];
#pragma unroll
    for (int mt = 0; mt < 2; ++mt)
#pragma unroll
        for (int nt = 0; nt < 4; ++nt)
#pragma unroll
            for (int i = 0; i < 4; ++i) acc[mt][nt][i] = 0.f;

#pragma unroll 1
    for (int k0 = 0; k0 < DD; k0 += 8) {
        unsigned af[2][4];
#pragma unroll
        for (int mt = 0; mt < 2; ++mt) {
            const unsigned* q0 = a2s + (wm + mt * 16 + lane4) * QPAD + k0 + kc;
            af[mt][0] = q0[0];
            af[mt][2] = q0[4];
            af[mt][1] = q0[8 * QPAD];
            af[mt][3] = q0[8 * QPAD + 4];
        }
        unsigned bf[4][2];
#pragma unroll
        for (int nt = 0; nt < 4; ++nt) {
            const float* p = (k0 < 384) ? (pWU[nt] + k0) : (pWij[nt] + (k0 - 384));
            bf[nt][0] = f2tf(p[kc]);
            bf[nt][1] = f2tf(p[kc + 4]);
        }
#pragma unroll
        for (int mt = 0; mt < 2; ++mt)
#pragma unroll
            for (int nt = 0; nt < 4; ++nt)
                mma8(acc[mt][nt], af[mt], bf[nt]);
    }

    // Epilogue: h_hat = tanh(acc + bij); softmax over z groups; h update.
#pragma unroll
    for (int mt = 0; mt < 2; ++mt) {
#pragma unroll
        for (int nt = 0; nt < 4; ++nt) {
            const int row = wm + mt * 16 + lane4;
            const int ub  = wn + nt * 8 + (lane & 3) * 2;
#pragma unroll
            for (int hrow = 0; hrow < 2; ++hrow) {
                const int b = b0 + row + hrow * 8;
#pragma unroll
                for (int cc = 0; cc < 2; ++cc) {
                    const int u = ub + cc;
                    const float pre = acc[mt][nt][hrow * 2 + cc] + bij[u];
                    const float hh = tanhf(pre);
                    const float* zp = lgbase + b * NOUT + 384 + u;
                    const float z0 = zp[0], z1 = zp[128], z2 = zp[256], z3 = zp[384];
                    const float m  = fmaxf(fmaxf(z0, z1), fmaxf(z2, z3));
                    const float e0 = __expf(z0 - m), e1 = __expf(z1 - m);
                    const float e2 = __expf(z2 - m), e3 = __expf(z3 - m);
                    const float inv = 1.f / (e0 + e1 + e2 + e3);
                    const float hlv = hl ? hl[b * UD + u] : 0.f;
                    const float htv = ht ? ht[b * UD + u] : 0.f;
                    const float hdv = hd ? hd[b * UD + u] : 0.f;
                    const float h = (e1 * hlv + e2 * htv + e3 * hdv + e0 * hh) * inv;
                    g_h[pc][l][b][u] = h;
                    if (d == NDIAG - 1) out[b * UD + u] = h;
                }
            }
        }
    }
}

// ---------------------------------------------------------------------------
extern "C" void kernel_launch(void* const* d_in, const int* in_sizes, int n_in,
                              void* d_out, int out_size)
{
    const float* inputs = (const float*)d_in[0];
    const float* Wr     = (const float*)d_in[1];
    const float* br     = (const float*)d_in[2];
    const float* Wz     = (const float*)d_in[3];
    const float* bz     = (const float*)d_in[4];
    const float* Wij    = (const float*)d_in[5];
    const float* bij    = (const float*)d_in[6];
    const float* WU     = (const float*)d_in[7];
    float* out = (float*)d_out;

    const int SMEM_A = BATCH * QPAD * (int)sizeof(unsigned); // 215040 B
    const int SMEM_B = 64    * QPAD * (int)sizeof(unsigned); // 107520 B
    cudaFuncSetAttribute(gemm1_kernel,
                         cudaFuncAttributeMaxDynamicSharedMemorySize, SMEM_A);
    cudaFuncSetAttribute(cell_update_kernel,
                         cudaFuncAttributeMaxDynamicSharedMemorySize, SMEM_B);

    for (int d = 0; d < NDIAG; ++d) {
        const int l0 = (d > RDIM - 1) ? d - (RDIM - 1) : 0;
        const int l1 = (d < LDIM - 1) ? d : LDIM - 1;
        const int nc = l1 - l0 + 1;
        gemm1_kernel<<<dim3(nc, 7), 256, SMEM_A>>>(inputs, Wr, br, Wz, bz, d, l0);
        cell_update_kernel<<<dim3(nc, 2), 256, SMEM_B>>>(inputs, Wij, bij, WU, out, d, l0);
    }
}

// round 2
// speedup vs baseline: 1.8632x; 1.8632x over previous
#include <cuda_runtime.h>

#define LDIM 80
#define RDIM 80
#define BATCH 128
#define UD 128
#define CD 32
#define DD 416
#define NOUT 896
#define NDIAG 159
#define KB 52
#define KBP 53

// Rotating h storage: slot d%3 holds h of all cells on diagonal d.
__device__ float g_h[3][LDIM][BATCH][UD];
// Per-diagonal GEMM1 logits scratch, indexed by cell-in-diagonal.
__device__ float g_logits[LDIM][BATCH][NOUT];
// Fragment-packed tf32 weights: j-blocks 0..111 = [Wr;Wz], 112..127 = [WU|Wij]
__device__ unsigned g_wpack[128][KBP][32][2];
__device__ unsigned g_count;
__device__ unsigned g_sense;

__device__ __forceinline__ unsigned f2tf(float x) {
    unsigned u;
    asm("cvt.rna.tf32.f32 %0, %1;" : "=r"(u) : "f"(x));
    return u;
}

__device__ __forceinline__ void mma8(float* c, const uint4& a, const uint2& b) {
    asm volatile(
        "mma.sync.aligned.m16n8k8.row.col.f32.tf32.tf32.f32 "
        "{%0,%1,%2,%3}, {%4,%5,%6,%7}, {%8,%9}, {%0,%1,%2,%3};\n"
        : "+f"(c[0]), "+f"(c[1]), "+f"(c[2]), "+f"(c[3])
        : "r"(a.x), "r"(a.y), "r"(a.z), "r"(a.w), "r"(b.x), "r"(b.y));
}

__device__ __forceinline__ void gbar(int ncta, unsigned& sense) {
    __syncthreads();
    if (threadIdx.x == 0) {
        __threadfence();
        unsigned arrived = atomicAdd(&g_count, 1u) + 1u;
        if (arrived == (unsigned)ncta) {
            g_count = 0u;
            __threadfence();
            atomicAdd(&g_sense, 1u);
        } else {
            while ((int)(*(volatile unsigned*)&g_sense - (sense + 1u)) < 0) {
                __nanosleep(64);
            }
        }
    }
    sense += 1u;
    __syncthreads();
}

__global__ __launch_bounds__(256) void spatial_gru_persist(
    const float* __restrict__ inputs, const float* __restrict__ Wr,
    const float* __restrict__ br, const float* __restrict__ Wz,
    const float* __restrict__ bz, const float* __restrict__ Wij,
    const float* __restrict__ bij, const float* __restrict__ WU,
    float* __restrict__ out, int ncta)
{
    extern __shared__ unsigned smem[];
    const int tid = threadIdx.x;
    const int cta = blockIdx.x;
    unsigned sense = *(volatile unsigned*)&g_sense;

    // ---------------- stage 0: pack weights into fragment order ------------
    for (int idx = cta * 256 + tid; idx < 128 * KB * 32; idx += ncta * 256) {
        const int lane = idx & 31;
        const int kblk = (idx >> 5) % KB;
        const int jblk = (idx >> 5) / KB;
        const int j = jblk * 8 + (lane >> 2);
        const int k = kblk * 8 + (lane & 3);
        float v0, v1;
        if (j < 384)      { v0 = Wr[j * DD + k];          v1 = Wr[j * DD + k + 4]; }
        else if (j < 896) { v0 = Wz[(j - 384) * DD + k];  v1 = Wz[(j - 384) * DD + k + 4]; }
        else {
            const int u = j - 896;
            v0 = (k < 384)     ? WU[u * 384 + k]     : Wij[u * 32 + (k - 384)];
            v1 = (k + 4 < 384) ? WU[u * 384 + k + 4] : Wij[u * 32 + (k - 380)];
        }
        g_wpack[jblk][kblk][lane][0] = f2tf(v0);
        g_wpack[jblk][kblk][lane][1] = f2tf(v1);
    }
    gbar(ncta, sense);

    const int warp = tid >> 5, lane = tid & 31;
    const int el4 = lane >> 2;

    for (int d = 0; d < NDIAG; ++d) {
        const int l0 = (d > RDIM - 1) ? d - (RDIM - 1) : 0;
        const int l1 = (d < LDIM - 1) ? d : LDIM - 1;
        const int nc = l1 - l0 + 1;
        const int p1 = (d + 2) % 3, p2 = (d + 1) % 3, pc = d % 3;

        // ============================ PHASE A ===============================
        for (int t = cta; t < nc * 7; t += ncta) {
            const int ci = t % nc, nchunk = t / nc;
            const int l = l0 + ci, rr = d - l;
            const float* htop  = (l > 0)            ? &g_h[p1][l - 1][0][0] : (const float*)0;
            const float* hleft = (rr > 0)           ? &g_h[p1][l][0][0]     : (const float*)0;
            const float* hdiag = (l > 0 && rr > 0)  ? &g_h[p2][l - 1][0][0] : (const float*)0;
            __syncthreads();
            // build swizzled q fragments in smem
            for (int idx = tid; idx < BATCH * 104; idx += 256) {
                const int b = idx / 104;
                const int k = (idx - b * 104) * 4;
                float v0, v1, v2, v3;
                if (k < 384) {
                    const float* src; int kk;
                    if (k < 128)      { src = htop;  kk = k; }
                    else if (k < 256) { src = hleft; kk = k - 128; }
                    else              { src = hdiag; kk = k - 256; }
                    if (src) {
                        float4 tv = __ldcg((const float4*)(src + b * UD + kk));
                        v0 = tv.x; v1 = tv.y; v2 = tv.z; v3 = tv.w;
                    } else { v0 = v1 = v2 = v3 = 0.f; }
                } else {
                    const int c = k - 384;
                    const float* sp = inputs + (((size_t)b * CD + c) * LDIM + l) * RDIM + rr;
                    v0 = sp[0];
                    v1 = sp[LDIM * RDIM];
                    v2 = sp[2 * LDIM * RDIM];
                    v3 = sp[3 * LDIM * RDIM];
                }
                const int mblk = b >> 4;
                const int r = b & 15;
                const int rl4 = r & 7, hi = r >> 3;
                const int kblk = k >> 3, khalf = (k >> 2) & 1;
                const int slot = hi + 2 * khalf;
                unsigned* qd = smem + ((mblk * KB + kblk) * 32 + rl4 * 4) * 4 + slot;
                qd[0] = f2tf(v0); qd[4] = f2tf(v1); qd[8] = f2tf(v2); qd[12] = f2tf(v3);
            }
            __syncthreads();

            const int wmblk = (warp & 1) * 4;
            const int wn = (warp >> 1) * 32;
            const int jblk0 = nchunk * 16 + (wn >> 3);

            float acc[4][4][4];
#pragma unroll
            for (int mt = 0; mt < 4; ++mt)
#pragma unroll
                for (int nt = 0; nt < 4; ++nt)
#pragma unroll
                    for (int i = 0; i < 4; ++i) acc[mt][nt][i] = 0.f;

            uint2 cur[4];
#pragma unroll
            for (int nt = 0; nt < 4; ++nt)
                cur[nt] = __ldcg((const uint2*)&g_wpack[jblk0 + nt][0][lane][0]);

#pragma unroll 4
            for (int kblk = 0; kblk < KB; ++kblk) {
                uint2 nxt[4];
#pragma unroll
                for (int nt = 0; nt < 4; ++nt)
                    nxt[nt] = __ldcg((const uint2*)&g_wpack[jblk0 + nt][kblk + 1][lane][0]);
                uint4 av[4];
#pragma unroll
                for (int mt = 0; mt < 4; ++mt)
                    av[mt] = *(const uint4*)(smem + (((wmblk + mt) * KB + kblk) * 32 + lane) * 4);
#pragma unroll
                for (int mt = 0; mt < 4; ++mt)
#pragma unroll
                    for (int nt = 0; nt < 4; ++nt)
                        mma8(acc[mt][nt], av[mt], cur[nt]);
#pragma unroll
                for (int nt = 0; nt < 4; ++nt) cur[nt] = nxt[nt];
            }

            float* lgb = &g_logits[ci][0][0];
#pragma unroll
            for (int nt = 0; nt < 4; ++nt) {
                const int col = nchunk * 128 + wn + nt * 8 + (lane & 3) * 2;
                float b0, b1;
                if (col < 384) { b0 = br[col];       b1 = br[col + 1]; }
                else           { b0 = bz[col - 384]; b1 = bz[col - 383]; }
#pragma unroll
                for (int mt = 0; mt < 4; ++mt) {
                    const int row = (wmblk + mt) * 16 + el4;
                    __stcg((float2*)(lgb + row * NOUT + col),
                           make_float2(acc[mt][nt][0] + b0, acc[mt][nt][1] + b1));
                    __stcg((float2*)(lgb + (row + 8) * NOUT + col),
                           make_float2(acc[mt][nt][2] + b0, acc[mt][nt][3] + b1));
                }
            }
        }
        gbar(ncta, sense);

        // ============================ PHASE B ===============================
        for (int t = cta; t < nc * 2; t += ncta) {
            const int ci = t >> 1, bh = t & 1;
            const int l = l0 + ci, rr = d - l;
            const int b0 = bh * 64;
            const float* hl = (rr > 0)           ? &g_h[p1][l][0][0]     : (const float*)0;
            const float* ht = (l > 0)            ? &g_h[p1][l - 1][0][0] : (const float*)0;
            const float* hd = (l > 0 && rr > 0)  ? &g_h[p2][l - 1][0][0] : (const float*)0;
            const float* lgb = &g_logits[ci][0][0];
            __syncthreads();
            // build swizzled A2 = [sig(r)*h | s] fragments
            for (int idx = tid; idx < 64 * 104; idx += 256) {
                const int bl = idx / 104;
                const int k = (idx - bl * 104) * 4;
                const int b = b0 + bl;
                float v0, v1, v2, v3;
                if (k < 384) {
                    const float* hsrc; int kk;
                    if (k < 128)      { hsrc = hl; kk = k; }
                    else if (k < 256) { hsrc = ht; kk = k - 128; }
                    else              { hsrc = hd; kk = k - 256; }
                    float4 lg = __ldcg((const float4*)(lgb + b * NOUT + k));
                    float4 hv = hsrc ? __ldcg((const float4*)(hsrc + b * UD + kk))
                                     : make_float4(0.f, 0.f, 0.f, 0.f);
                    v0 = hv.x / (1.f + __expf(-lg.x));
                    v1 = hv.y / (1.f + __expf(-lg.y));
                    v2 = hv.z / (1.f + __expf(-lg.z));
                    v3 = hv.w / (1.f + __expf(-lg.w));
                } else {
                    const int c = k - 384;
                    const float* sp = inputs + (((size_t)b * CD + c) * LDIM + l) * RDIM + rr;
                    v0 = sp[0];
                    v1 = sp[LDIM * RDIM];
                    v2 = sp[2 * LDIM * RDIM];
                    v3 = sp[3 * LDIM * RDIM];
                }
                const int mblk = bl >> 4;
                const int r = bl & 15;
                const int rl4 = r & 7, hi = r >> 3;
                const int kblk = k >> 3, khalf = (k >> 2) & 1;
                const int slot = hi + 2 * khalf;
                unsigned* qd = smem + ((mblk * KB + kblk) * 32 + rl4 * 4) * 4 + slot;
                qd[0] = f2tf(v0); qd[4] = f2tf(v1); qd[8] = f2tf(v2); qd[12] = f2tf(v3);
            }
            __syncthreads();

            const int wmblk = (warp & 1) * 2;
            const int wn = (warp >> 1) * 32;
            const int jblk0 = 112 + (wn >> 3);

            float acc[2][4][4];
#pragma unroll
            for (int mt = 0; mt < 2; ++mt)
#pragma unroll
                for (int nt = 0; nt < 4; ++nt)
#pragma unroll
                    for (int i = 0; i < 4; ++i) acc[mt][nt][i] = 0.f;

            uint2 cur[4];
#pragma unroll
            for (int nt = 0; nt < 4; ++nt)
                cur[nt] = __ldcg((const uint2*)&g_wpack[jblk0 + nt][0][lane][0]);

#pragma unroll 4
            for (int kblk = 0; kblk < KB; ++kblk) {
                uint2 nxt[4];
#pragma unroll
                for (int nt = 0; nt < 4; ++nt)
                    nxt[nt] = __ldcg((const uint2*)&g_wpack[jblk0 + nt][kblk + 1][lane][0]);
                uint4 av[2];
#pragma unroll
                for (int mt = 0; mt < 2; ++mt)
                    av[mt] = *(const uint4*)(smem + (((wmblk + mt) * KB + kblk) * 32 + lane) * 4);
#pragma unroll
                for (int mt = 0; mt < 2; ++mt)
#pragma unroll
                    for (int nt = 0; nt < 4; ++nt)
                        mma8(acc[mt][nt], av[mt], cur[nt]);
#pragma unroll
                for (int nt = 0; nt < 4; ++nt) cur[nt] = nxt[nt];
            }
            __syncthreads();

            // cooperative softmax + h-mix pass into smem (a2 region now dead)
            float* hmix_s = (float*)smem;
            float* zi_s = hmix_s + 64 * 128;
            for (int idx = tid; idx < 64 * 128; idx += 256) {
                const int bl = idx >> 7, u = idx & 127;
                const int b = b0 + bl;
                const float* zp = lgb + b * NOUT + 384 + u;
                const float z0 = __ldcg(zp), z1 = __ldcg(zp + 128);
                const float z2 = __ldcg(zp + 256), z3 = __ldcg(zp + 384);
                const float m = fmaxf(fmaxf(z0, z1), fmaxf(z2, z3));
                const float e0 = __expf(z0 - m), e1 = __expf(z1 - m);
                const float e2 = __expf(z2 - m), e3 = __expf(z3 - m);
                const float inv = 1.f / (e0 + e1 + e2 + e3);
                const float hlv = hl ? __ldcg(hl + b * UD + u) : 0.f;
                const float htv = ht ? __ldcg(ht + b * UD + u) : 0.f;
                const float hdv = hd ? __ldcg(hd + b * UD + u) : 0.f;
                hmix_s[idx] = (e1 * hlv + e2 * htv + e3 * hdv) * inv;
                zi_s[idx]   = e0 * inv;
            }
            __syncthreads();

            float* hout = &g_h[pc][l][0][0];
#pragma unroll
            for (int nt = 0; nt < 4; ++nt) {
                const int u0 = wn + nt * 8 + (lane & 3) * 2;
                const float2 bj = *(const float2*)(bij + u0);
#pragma unroll
                for (int mt = 0; mt < 2; ++mt) {
                    const int rl = (wmblk + mt) * 16 + el4;
#pragma unroll
                    for (int hr = 0; hr < 2; ++hr) {
                        const int rloc = rl + hr * 8;
                        const int b = b0 + rloc;
                        const float hh0 = tanhf(acc[mt][nt][hr * 2 + 0] + bj.x);
                        const float hh1 = tanhf(acc[mt][nt][hr * 2 + 1] + bj.y);
                        const float2 hm = *(const float2*)(hmix_s + rloc * 128 + u0);
                        const float2 zi = *(const float2*)(zi_s + rloc * 128 + u0);
                        const float h0 = hm.x + zi.x * hh0;
                        const float h1 = hm.y + zi.y * hh1;
                        __stcg((float2*)(hout + b * UD + u0), make_float2(h0, h1));
                        if (d == NDIAG - 1)
                            *(float2*)(out + b * UD + u0) = make_float2(h0, h1);
                    }
                }
            }
        }
        gbar(ncta, sense);
    }
}

// ---------------------------------------------------------------------------
extern "C" void kernel_launch(void* const* d_in, const int* in_sizes, int n_in,
                              void* d_out, int out_size)
{
    const float* inputs = (const float*)d_in[0];
    const float* Wr     = (const float*)d_in[1];
    const float* br     = (const float*)d_in[2];
    const float* Wz     = (const float*)d_in[3];
    const float* bz     = (const float*)d_in[4];
    const float* Wij    = (const float*)d_in[5];
    const float* bij    = (const float*)d_in[6];
    const float* WU     = (const float*)d_in[7];
    float* out = (float*)d_out;

    const int SMEM = 8 * KB * 32 * 4 * (int)sizeof(unsigned);  // 212992
    cudaFuncSetAttribute(spatial_gru_persist,
                         cudaFuncAttributeMaxDynamicSharedMemorySize, SMEM);
    int dev = 0;
    cudaGetDevice(&dev);
    int nsm = 0;
    cudaDeviceGetAttribute(&nsm, cudaDevAttrMultiProcessorCount, dev);
    int occ = 0;
    cudaOccupancyMaxActiveBlocksPerMultiprocessor(&occ, spatial_gru_persist, 256, SMEM);
    if (occ < 1) occ = 1;
    const int ncta = nsm * occ;

    spatial_gru_persist<<<ncta, 256, SMEM>>>(inputs, Wr, br, Wz, bz, Wij, bij,
                                             WU, out, ncta);
}

// round 3
// speedup vs baseline: 2.8568x; 1.5333x over previous
#include <cuda_runtime.h>

#define LDIM 80
#define RDIM 80
#define BATCH 128
#define UD 128
#define CD 32
#define DD 416
#define NOUT 896
#define NDIAG 159
#define KB 52
#define KBP 53

// Full h storage for every cell (no rotation: pipelining-safe).
__device__ float    g_hfull[LDIM][RDIM][BATCH][UD];      // 419 MB
// Logits scratch, slot keyed by l (reuse protected by left-dependency).
__device__ float    g_logits[LDIM][BATCH][NOUT];         // 36.7 MB
// Pre-transposed tf32 inputs: (l, r, b, c).
__device__ unsigned g_sT[LDIM][RDIM][BATCH][CD];         // 104 MB
// Fragment-packed tf32 weights: jblk 0..111 = [Wr;Wz], 112..127 = [WU|Wij]
__device__ unsigned g_wpack[128][KBP][32][2];
// Dataflow flags (reset every run).
__device__ unsigned g_hflag[LDIM][RDIM][2];
__device__ unsigned g_lcnt[LDIM][2];
__device__ unsigned g_count;
__device__ unsigned g_sense;

__device__ __forceinline__ unsigned f2tf(float x) {
    unsigned u;
    asm("cvt.rna.tf32.f32 %0, %1;" : "=r"(u) : "f"(x));
    return u;
}

__device__ __forceinline__ void mma8(float* c, const uint4& a, const uint2& b) {
    asm volatile(
        "mma.sync.aligned.m16n8k8.row.col.f32.tf32.tf32.f32 "
        "{%0,%1,%2,%3}, {%4,%5,%6,%7}, {%8,%9}, {%0,%1,%2,%3};\n"
        : "+f"(c[0]), "+f"(c[1]), "+f"(c[2]), "+f"(c[3])
        : "r"(a.x), "r"(a.y), "r"(a.z), "r"(a.w), "r"(b.x), "r"(b.y));
}

__device__ __forceinline__ void gbar(int ncta, unsigned& sense) {
    __syncthreads();
    if (threadIdx.x == 0) {
        __threadfence();
        unsigned arrived = atomicAdd(&g_count, 1u) + 1u;
        if (arrived == (unsigned)ncta) {
            g_count = 0u;
            __threadfence();
            atomicAdd(&g_sense, 1u);
        } else {
            while ((int)(*(volatile unsigned*)&g_sense - (sense + 1u)) < 0) {
                __nanosleep(64);
            }
        }
    }
    sense += 1u;
    __syncthreads();
}

__global__ __launch_bounds__(256, 2) void spatial_gru_flow(
    const float* __restrict__ inputs, const float* __restrict__ Wr,
    const float* __restrict__ br, const float* __restrict__ Wz,
    const float* __restrict__ bz, const float* __restrict__ Wij,
    const float* __restrict__ bij, const float* __restrict__ WU,
    float* __restrict__ out, int ncta)
{
    extern __shared__ unsigned smem[];
    const int tid = threadIdx.x;
    const int cta = blockIdx.x;
    const int gtid = cta * 256 + tid;
    const int gstride = ncta * 256;
    unsigned sense = *(volatile unsigned*)&g_sense;

    // ---------------- stage 0: pack weights, transpose s, reset flags ------
    for (int idx = gtid; idx < 128 * KB * 32; idx += gstride) {
        const int lane = idx & 31;
        const int kblk = (idx >> 5) % KB;
        const int jblk = (idx >> 5) / KB;
        const int j = jblk * 8 + (lane >> 2);
        const int k = kblk * 8 + (lane & 3);
        float v0, v1;
        if (j < 384)      { v0 = Wr[j * DD + k];          v1 = Wr[j * DD + k + 4]; }
        else if (j < 896) { v0 = Wz[(j - 384) * DD + k];  v1 = Wz[(j - 384) * DD + k + 4]; }
        else {
            const int u = j - 896;
            v0 = (k < 384)     ? WU[u * 384 + k]     : Wij[u * 32 + (k - 384)];
            v1 = (k + 4 < 384) ? WU[u * 384 + k + 4] : Wij[u * 32 + (k - 380)];
        }
        g_wpack[jblk][kblk][lane][0] = f2tf(v0);
        g_wpack[jblk][kblk][lane][1] = f2tf(v1);
    }
    // transpose inputs (B,C,L,R) -> tf32 (L,R,B,C)
    for (int idx = gtid; idx < LDIM * RDIM * BATCH * (CD / 4); idx += gstride) {
        const int c4 = idx & 7;
        const int b  = (idx >> 3) & 127;
        const int r  = (idx >> 10) % RDIM;
        const int l  = (idx >> 10) / RDIM;
        const int c  = c4 * 4;
        const float* sp = inputs + (((size_t)b * CD + c) * LDIM + l) * RDIM + r;
        unsigned* dst = &g_sT[l][r][b][c];
        dst[0] = f2tf(sp[0]);
        dst[1] = f2tf(sp[LDIM * RDIM]);
        dst[2] = f2tf(sp[2 * LDIM * RDIM]);
        dst[3] = f2tf(sp[3 * LDIM * RDIM]);
    }
    for (int idx = gtid; idx < LDIM * RDIM * 2; idx += gstride)
        ((unsigned*)g_hflag)[idx] = 0u;
    for (int idx = gtid; idx < LDIM * 2; idx += gstride)
        ((unsigned*)g_lcnt)[idx] = 0u;
    gbar(ncta, sense);

    const int warp = tid >> 5, lane = tid & 31;
    const int el4 = lane >> 2;
    const int wmblk = (warp & 1) * 2;          // 2 m-blocks (32 rows) per warp
    const int wn = (warp >> 1) * 32;           // 32 cols per warp

    int base = 0;
    for (int d = 0; d < NDIAG; ++d) {
        const int l0 = (d > RDIM - 1) ? d - (RDIM - 1) : 0;
        const int l1 = (d < LDIM - 1) ? d : LDIM - 1;
        const int nc = l1 - l0 + 1;
        const int Td = 16 * nc;
        int t0 = cta - (base % ncta);
        if (t0 < 0) t0 += ncta;

        for (int t = t0; t < Td; t += ncta) {
            if (t < nc * 14) {
                // ======================= A tile ============================
                const int ci = t / 14, sub = t - ci * 14;
                const int hb = sub / 7, nch = sub - hb * 7;
                const int l = l0 + ci, rr = d - l;
                const int b0 = hb * 64;

                if (tid < 3) {
                    volatile unsigned* f = 0;
                    if (tid == 0)      { if (rr > 0) f = &g_hflag[l][rr - 1][hb]; }
                    else if (tid == 1) { if (l > 0)  f = &g_hflag[l - 1][rr][hb]; }
                    else               { if (l > 0 && rr > 0) f = &g_hflag[l - 1][rr - 1][hb]; }
                    if (f) {
                        while (*f == 0u) __nanosleep(40);
                        __threadfence();
                    }
                }
                __syncthreads();

                const float* htop  = (l > 0)           ? &g_hfull[l - 1][rr][0][0]     : (const float*)0;
                const float* hleft = (rr > 0)          ? &g_hfull[l][rr - 1][0][0]     : (const float*)0;
                const float* hdiag = (l > 0 && rr > 0) ? &g_hfull[l - 1][rr - 1][0][0] : (const float*)0;

                for (int idx = tid; idx < 64 * 104; idx += 256) {
                    const int bl = idx / 104;
                    const int k = (idx - bl * 104) * 4;
                    const int b = b0 + bl;
                    unsigned w0, w1, w2, w3;
                    if (k < 384) {
                        const float* src; int kk;
                        if (k < 128)      { src = htop;  kk = k; }
                        else if (k < 256) { src = hleft; kk = k - 128; }
                        else              { src = hdiag; kk = k - 256; }
                        if (src) {
                            float4 tv = __ldcg((const float4*)(src + b * UD + kk));
                            w0 = f2tf(tv.x); w1 = f2tf(tv.y);
                            w2 = f2tf(tv.z); w3 = f2tf(tv.w);
                        } else { w0 = w1 = w2 = w3 = 0u; }
                    } else {
                        const uint4 sv = *(const uint4*)&g_sT[l][rr][b][k - 384];
                        w0 = sv.x; w1 = sv.y; w2 = sv.z; w3 = sv.w;
                    }
                    const int mblk = bl >> 4;
                    const int rl = bl & 15;
                    const int rl4 = rl & 7, hi = rl >> 3;
                    const int kblk = k >> 3, khalf = (k >> 2) & 1;
                    unsigned* qd = smem + ((mblk * KB + kblk) * 32 + rl4 * 4) * 4 + hi + 2 * khalf;
                    qd[0] = w0; qd[4] = w1; qd[8] = w2; qd[12] = w3;
                }
                __syncthreads();

                const int jblk0 = nch * 16 + (wn >> 3);
                float acc[2][4][4];
#pragma unroll
                for (int mt = 0; mt < 2; ++mt)
#pragma unroll
                    for (int nt = 0; nt < 4; ++nt)
#pragma unroll
                        for (int i = 0; i < 4; ++i) acc[mt][nt][i] = 0.f;
                uint2 cur[4];
#pragma unroll
                for (int nt = 0; nt < 4; ++nt)
                    cur[nt] = __ldcg((const uint2*)&g_wpack[jblk0 + nt][0][lane][0]);
#pragma unroll 4
                for (int kblk = 0; kblk < KB; ++kblk) {
                    uint2 nxt[4];
#pragma unroll
                    for (int nt = 0; nt < 4; ++nt)
                        nxt[nt] = __ldcg((const uint2*)&g_wpack[jblk0 + nt][kblk + 1][lane][0]);
                    uint4 av[2];
#pragma unroll
                    for (int mt = 0; mt < 2; ++mt)
                        av[mt] = *(const uint4*)(smem + (((wmblk + mt) * KB + kblk) * 32 + lane) * 4);
#pragma unroll
                    for (int mt = 0; mt < 2; ++mt)
#pragma unroll
                        for (int nt = 0; nt < 4; ++nt)
                            mma8(acc[mt][nt], av[mt], cur[nt]);
#pragma unroll
                    for (int nt = 0; nt < 4; ++nt) cur[nt] = nxt[nt];
                }

                float* lgb = &g_logits[l][0][0];
#pragma unroll
                for (int nt = 0; nt < 4; ++nt) {
                    const int col = nch * 128 + wn + nt * 8 + (lane & 3) * 2;
                    float bb0, bb1;
                    if (col < 384) { bb0 = br[col];       bb1 = br[col + 1]; }
                    else           { bb0 = bz[col - 384]; bb1 = bz[col - 383]; }
#pragma unroll
                    for (int mt = 0; mt < 2; ++mt) {
                        const int row = b0 + (wmblk + mt) * 16 + el4;
                        __stcg((float2*)(lgb + row * NOUT + col),
                               make_float2(acc[mt][nt][0] + bb0, acc[mt][nt][1] + bb1));
                        __stcg((float2*)(lgb + (row + 8) * NOUT + col),
                               make_float2(acc[mt][nt][2] + bb0, acc[mt][nt][3] + bb1));
                    }
                }
                __threadfence();
                __syncthreads();
                if (tid == 0) atomicAdd(&g_lcnt[l][hb], 1u);
            } else {
                // ======================= B tile ============================
                const int u2 = t - nc * 14;
                const int ci = u2 >> 1, hb = u2 & 1;
                const int l = l0 + ci, rr = d - l;
                const int b0 = hb * 64;
                const unsigned expected = 7u * (unsigned)(rr + 1);

                if (tid == 0) {
                    volatile unsigned* c = &g_lcnt[l][hb];
                    while (*c < expected) __nanosleep(40);
                    __threadfence();
                }
                __syncthreads();

                const float* hl = (rr > 0)          ? &g_hfull[l][rr - 1][0][0]     : (const float*)0;
                const float* ht = (l > 0)           ? &g_hfull[l - 1][rr][0][0]     : (const float*)0;
                const float* hd = (l > 0 && rr > 0) ? &g_hfull[l - 1][rr - 1][0][0] : (const float*)0;
                const float* lgb = &g_logits[l][0][0];

                for (int idx = tid; idx < 64 * 104; idx += 256) {
                    const int bl = idx / 104;
                    const int k = (idx - bl * 104) * 4;
                    const int b = b0 + bl;
                    unsigned w0, w1, w2, w3;
                    if (k < 384) {
                        const float* hsrc; int kk;
                        if (k < 128)      { hsrc = hl; kk = k; }
                        else if (k < 256) { hsrc = ht; kk = k - 128; }
                        else              { hsrc = hd; kk = k - 256; }
                        float4 lg = __ldcg((const float4*)(lgb + b * NOUT + k));
                        float4 hv = hsrc ? __ldcg((const float4*)(hsrc + b * UD + kk))
                                         : make_float4(0.f, 0.f, 0.f, 0.f);
                        w0 = f2tf(hv.x / (1.f + __expf(-lg.x)));
                        w1 = f2tf(hv.y / (1.f + __expf(-lg.y)));
                        w2 = f2tf(hv.z / (1.f + __expf(-lg.z)));
                        w3 = f2tf(hv.w / (1.f + __expf(-lg.w)));
                    } else {
                        const uint4 sv = *(const uint4*)&g_sT[l][rr][b][k - 384];
                        w0 = sv.x; w1 = sv.y; w2 = sv.z; w3 = sv.w;
                    }
                    const int mblk = bl >> 4;
                    const int rl = bl & 15;
                    const int rl4 = rl & 7, hi = rl >> 3;
                    const int kblk = k >> 3, khalf = (k >> 2) & 1;
                    unsigned* qd = smem + ((mblk * KB + kblk) * 32 + rl4 * 4) * 4 + hi + 2 * khalf;
                    qd[0] = w0; qd[4] = w1; qd[8] = w2; qd[12] = w3;
                }
                __syncthreads();

                const int jblk0 = 112 + (wn >> 3);
                float acc[2][4][4];
#pragma unroll
                for (int mt = 0; mt < 2; ++mt)
#pragma unroll
                    for (int nt = 0; nt < 4; ++nt)
#pragma unroll
                        for (int i = 0; i < 4; ++i) acc[mt][nt][i] = 0.f;
                uint2 cur[4];
#pragma unroll
                for (int nt = 0; nt < 4; ++nt)
                    cur[nt] = __ldcg((const uint2*)&g_wpack[jblk0 + nt][0][lane][0]);
#pragma unroll 4
                for (int kblk = 0; kblk < KB; ++kblk) {
                    uint2 nxt[4];
#pragma unroll
                    for (int nt = 0; nt < 4; ++nt)
                        nxt[nt] = __ldcg((const uint2*)&g_wpack[jblk0 + nt][kblk + 1][lane][0]);
                    uint4 av[2];
#pragma unroll
                    for (int mt = 0; mt < 2; ++mt)
                        av[mt] = *(const uint4*)(smem + (((wmblk + mt) * KB + kblk) * 32 + lane) * 4);
#pragma unroll
                    for (int mt = 0; mt < 2; ++mt)
#pragma unroll
                        for (int nt = 0; nt < 4; ++nt)
                            mma8(acc[mt][nt], av[mt], cur[nt]);
#pragma unroll
                    for (int nt = 0; nt < 4; ++nt) cur[nt] = nxt[nt];
                }
                __syncthreads();

                float* hmix_s = (float*)smem;
                float* zi_s = hmix_s + 64 * 128;
                for (int idx = tid; idx < 64 * 128; idx += 256) {
                    const int bl = idx >> 7, u = idx & 127;
                    const int b = b0 + bl;
                    const float* zp = lgb + b * NOUT + 384 + u;
                    const float z0 = __ldcg(zp), z1 = __ldcg(zp + 128);
                    const float z2 = __ldcg(zp + 256), z3 = __ldcg(zp + 384);
                    const float m = fmaxf(fmaxf(z0, z1), fmaxf(z2, z3));
                    const float e0 = __expf(z0 - m), e1 = __expf(z1 - m);
                    const float e2 = __expf(z2 - m), e3 = __expf(z3 - m);
                    const float inv = 1.f / (e0 + e1 + e2 + e3);
                    const float hlv = hl ? __ldcg(hl + b * UD + u) : 0.f;
                    const float htv = ht ? __ldcg(ht + b * UD + u) : 0.f;
                    const float hdv = hd ? __ldcg(hd + b * UD + u) : 0.f;
                    hmix_s[idx] = (e1 * hlv + e2 * htv + e3 * hdv) * inv;
                    zi_s[idx]   = e0 * inv;
                }
                __syncthreads();

                float* hout = &g_hfull[l][rr][0][0];
#pragma unroll
                for (int nt = 0; nt < 4; ++nt) {
                    const int u0 = wn + nt * 8 + (lane & 3) * 2;
                    const float2 bj = *(const float2*)(bij + u0);
#pragma unroll
                    for (int mt = 0; mt < 2; ++mt) {
                        const int rl = (wmblk + mt) * 16 + el4;
#pragma unroll
                        for (int hr = 0; hr < 2; ++hr) {
                            const int rloc = rl + hr * 8;
                            const int b = b0 + rloc;
                            const float hh0 = tanhf(acc[mt][nt][hr * 2 + 0] + bj.x);
                            const float hh1 = tanhf(acc[mt][nt][hr * 2 + 1] + bj.y);
                            const float2 hm = *(const float2*)(hmix_s + rloc * 128 + u0);
                            const float2 zi = *(const float2*)(zi_s + rloc * 128 + u0);
                            const float h0 = hm.x + zi.x * hh0;
                            const float h1 = hm.y + zi.y * hh1;
                            __stcg((float2*)(hout + b * UD + u0), make_float2(h0, h1));
                            if (d == NDIAG - 1)
                                *(float2*)(out + b * UD + u0) = make_float2(h0, h1);
                        }
                    }
                }
                __threadfence();
                __syncthreads();
                if (tid == 0) *(volatile unsigned*)&g_hflag[l][rr][hb] = 1u;
            }
        }
        base += Td;
    }
}

// ---------------------------------------------------------------------------
extern "C" void kernel_launch(void* const* d_in, const int* in_sizes, int n_in,
                              void* d_out, int out_size)
{
    const float* inputs = (const float*)d_in[0];
    const float* Wr     = (const float*)d_in[1];
    const float* br     = (const float*)d_in[2];
    const float* Wz     = (const float*)d_in[3];
    const float* bz     = (const float*)d_in[4];
    const float* Wij    = (const float*)d_in[5];
    const float* bij    = (const float*)d_in[6];
    const float* WU     = (const float*)d_in[7];
    float* out = (float*)d_out;

    const int SMEM = 4 * KB * 32 * 4 * (int)sizeof(unsigned);  // 106496 B
    cudaFuncSetAttribute(spatial_gru_flow,
                         cudaFuncAttributeMaxDynamicSharedMemorySize, SMEM);
    int dev = 0;
    cudaGetDevice(&dev);
    int nsm = 0;
    cudaDeviceGetAttribute(&nsm, cudaDevAttrMultiProcessorCount, dev);
    int occ = 0;
    cudaOccupancyMaxActiveBlocksPerMultiprocessor(&occ, spatial_gru_flow, 256, SMEM);
    if (occ < 1) occ = 1;
    const int ncta = nsm * occ;   // grid == resident CTAs (deadlock-free dataflow)

    spatial_gru_flow<<<ncta, 256, SMEM>>>(inputs, Wr, br, Wz, bz, Wij, bij,
                                          WU, out, ncta);
}